// round 8
// baseline (speedup 1.0000x reference)
#include <cuda_runtime.h>

// SSIM loss: persistent 32-wide column-strip kernel with 42-row hb ring.
// pred/target: (16,3,512,512) f32. Output: scalar f32 = 1 - mean(ssim_map).
// Each block: 32 output cols x 128 output rows (4 chunks of 32 rows).
// Steady state computes each horizontal-blur row exactly once (amp 1.078 vs
// 1.31 for independent 32x32 tiles) and overlaps next-chunk global loads
// (warps 4-7) with the vertical pass (warps 0-3).
//
// Ring convention: hbG[i] lives at slot (i + 210) % 42 (210 = 5*42).
// s0 = slot of hbG[Y0-5]. New row hbG[Y0+37] = hbG[(Y0-5)+42] -> slot s0.

#define RAD 5
#define PWS 42                // strip width incl. halo (32 + 10)
#define RING 42               // hb ring rows
#define HB4P 33               // float4 pitch: 528B = 16 mod 128 -> conflict-free
#define HB5P 36               // float  pitch: 144B = 16 mod 128 -> conflict-free
#define IMG 512
#define NIMG 48
#define NBLK (64 * NIMG)      // 16 x-strips * 4 y-strips * 48 images = 3072
#define SSIM_C1 1.0e-4f
#define SSIM_C2 9.0e-4f

__device__ float g_bsum[NBLK];
__device__ int g_cnt;         // zero-init; last block resets each run

union F2U { float2 f; unsigned long long u; };

__device__ __forceinline__ unsigned long long pack2(float x, float y) {
    unsigned long long r;
    asm("mov.b64 %0, {%1, %2};" : "=l"(r) : "f"(x), "f"(y));
    return r;
}
__device__ __forceinline__ unsigned long long fma2(unsigned long long a,
                                                   unsigned long long b,
                                                   unsigned long long c) {
    unsigned long long d;
    asm("fma.rn.f32x2 %0, %1, %2, %3;" : "=l"(d) : "l"(a), "l"(b), "l"(c));
    return d;
}
__device__ __forceinline__ unsigned long long mul2(unsigned long long a,
                                                   unsigned long long b) {
    unsigned long long d;
    asm("mul.rn.f32x2 %0, %1, %2;" : "=l"(d) : "l"(a), "l"(b));
    return d;
}

// Normalized 1-D Gaussian, sigma=1.5, size 11.
__device__ __constant__ float c_GW[11] = {
    0.00102838f, 0.00759876f, 0.03600077f, 0.10936069f, 0.21300553f,
    0.26601173f,
    0.21300553f, 0.10936069f, 0.03600077f, 0.00759876f, 0.00102838f
};

// Load one halo row (42 float2 cells) into spt[r]. Zero-pads out of range.
__device__ __forceinline__ void load_row(float2 (&spt)[PWS][PWS], int r,
                                         const float* __restrict__ pb,
                                         const float* __restrict__ tb,
                                         int gy, int x0, bool xin, int lane)
{
    const bool rok = ((unsigned)gy < (unsigned)IMG);
    const float* prow = pb + gy * IMG;
    const float* trow = tb + gy * IMG;
    if (xin & rok) {
        const float* p = prow + x0;
        const float* t = trow + x0;
        spt[r][lane] = make_float2(__ldg(p + lane), __ldg(t + lane));
        if (lane < PWS - 32)
            spt[r][lane + 32] = make_float2(__ldg(p + lane + 32),
                                            __ldg(t + lane + 32));
    } else {
        int gx = x0 + lane;
        bool ok = rok && ((unsigned)gx < (unsigned)IMG);
        spt[r][lane] = ok ? make_float2(__ldg(prow + gx), __ldg(trow + gx))
                          : make_float2(0.f, 0.f);
        if (lane < PWS - 32) {
            gx += 32;
            ok = rok && ((unsigned)gx < (unsigned)IMG);
            spt[r][lane + 32] = ok ? make_float2(__ldg(prow + gx), __ldg(trow + gx))
                                   : make_float2(0.f, 0.f);
        }
    }
}

// Horizontal pass for one (row, 4-col group) item: read spt[r], write ring[slot].
__device__ __forceinline__ void hpass_one(const float2 (&spt)[PWS][PWS],
                                          float4 (&hb1234)[RING][HB4P],
                                          float (&hb5)[RING][HB5P],
                                          const unsigned long long* GWp,
                                          const float* GWs,
                                          int r, int cx, int slot)
{
    float4 raw[7];
    const float4* rp = reinterpret_cast<const float4*>(&spt[r][cx]);
    #pragma unroll
    for (int q = 0; q < 7; q++) raw[q] = rp[q];

    F2U acc12[4], acc34[4];
    float acc5[4];
    #pragma unroll
    for (int j = 0; j < 4; j++) {
        acc12[j].f = make_float2(0.f, 0.f);
        acc34[j].f = make_float2(0.f, 0.f);
        acc5[j] = 0.f;
    }

    #pragma unroll
    for (int k = 0; k < 14; k++) {
        F2U e;
        e.f.x = (k & 1) ? raw[k >> 1].z : raw[k >> 1].x;
        e.f.y = (k & 1) ? raw[k >> 1].w : raw[k >> 1].y;
        F2U sq; sq.u = mul2(e.u, e.u);
        const float x = e.f.x * e.f.y;
        #pragma unroll
        for (int j = 0; j < 4; j++) {
            const int w = k - j;
            if (w >= 0 && w < 11) {
                acc12[j].u = fma2(GWp[w], e.u,  acc12[j].u);
                acc34[j].u = fma2(GWp[w], sq.u, acc34[j].u);
                acc5[j]    = fmaf(GWs[w], x, acc5[j]);
            }
        }
    }

    #pragma unroll
    for (int j = 0; j < 4; j++)
        hb1234[slot][cx + j] = make_float4(acc12[j].f.x, acc12[j].f.y,
                                           acc34[j].f.x, acc34[j].f.y);
    *reinterpret_cast<float4*>(&hb5[slot][cx]) =
        make_float4(acc5[0], acc5[1], acc5[2], acc5[3]);
}

__global__ __launch_bounds__(256, 5)
void ssim_strip(const float* __restrict__ pred,
                const float* __restrict__ target,
                float* __restrict__ out)
{
    __shared__ float2 spt[PWS][PWS];          // chunk rows (42 for chunk0, 32 later)
    __shared__ float4 hb1234[RING][HB4P];     // (h(p), h(t), h(p^2), h(t^2)) ring
    __shared__ float  hb5[RING][HB5P];        // h(p*t) ring
    __shared__ float  wsum[4];
    __shared__ double dsum[8];
    __shared__ int    s_last;

    float GWs[11];
    unsigned long long GWp[11];
    #pragma unroll
    for (int k = 0; k < 11; k++) {
        GWs[k] = c_GW[k];
        GWp[k] = pack2(GWs[k], GWs[k]);
    }
    const unsigned long long NEG1 = pack2(-1.0f, -1.0f);

    const int tid  = threadIdx.x;
    const int lane = tid & 31;
    const int wrp  = tid >> 5;

    const int sx  = blockIdx.x & 15;          // x-strip
    const int sy  = blockIdx.x >> 4;          // y-strip (0..3)
    const int bid = blockIdx.y * 64 + blockIdx.x;
    const float* pb = pred   + (size_t)blockIdx.y * IMG * IMG;
    const float* tb = target + (size_t)blockIdx.y * IMG * IMG;
    const int x0 = sx * 32 - RAD;
    const int Y0 = sy * 128;
    const bool xin = (sx > 0) && (sx < 15);

    // Slot of hbG[Y0-5].
    const int s0 = (Y0 + 205) % 42;

    // ---- Chunk 0 prologue: load 42 halo rows, hpass all 42 --------------
    #pragma unroll 1
    for (int r = wrp; r < 42; r += 8)
        load_row(spt, r, pb, tb, Y0 - RAD + r, x0, xin, lane);
    __syncthreads();

    #pragma unroll
    for (int h2 = 0; h2 < 2; h2++) {
        const int it = tid + h2 * 256;
        if (it < 42 * 8) {
            const int g = it / 42;
            const int r = it - g * 42;
            int slot = s0 + r; if (slot >= 42) slot -= 42;
            hpass_one(spt, hb1234, hb5, GWp, GWs, r, g * 4, slot);
        }
    }
    __syncthreads();

    // Per-thread ring cursors.
    int sc = s0 + wrp * 8;  if (sc >= 42) sc -= 42;   // vpass base (wrp<4)
    int s2 = s0;   // hpass base for next chunk: hbG[Y0+37] = hbG[(Y0-5)+42] -> slot s0

    float ssum = 0.f;

    #pragma unroll 1
    for (int c = 0; c < 4; c++) {
        if (wrp < 4) {
            // ---- vertical pass + SSIM for chunk c (8 rows/thread) -------
            F2U a12[8], a34[8];
            float a5[8];
            #pragma unroll
            for (int j = 0; j < 8; j++) {
                a12[j].f = make_float2(0.f, 0.f);
                a34[j].f = make_float2(0.f, 0.f);
                a5[j] = 0.f;
            }

            #pragma unroll
            for (int k = 0; k < 18; k++) {
                int rs = sc + k; if (rs >= 42) rs -= 42;
                const float4 h = hb1234[rs][lane];
                F2U h12; h12.f = make_float2(h.x, h.y);
                F2U h34; h34.f = make_float2(h.z, h.w);
                const float h5 = hb5[rs][lane];
                #pragma unroll
                for (int j = 0; j < 8; j++) {
                    const int w = k - j;
                    if (w >= 0 && w < 11) {
                        a12[j].u = fma2(GWp[w], h12.u, a12[j].u);
                        a34[j].u = fma2(GWp[w], h34.u, a34[j].u);
                        a5[j]    = fmaf(GWs[w], h5, a5[j]);
                    }
                }
            }

            float num[8], den[8];
            #pragma unroll
            for (int j = 0; j < 8; j++) {
                F2U musq; musq.u = mul2(a12[j].u, a12[j].u);     // (mu1^2, mu2^2)
                F2U sig;  sig.u  = fma2(NEG1, musq.u, a34[j].u); // (sig1^2, sig2^2)
                const float mu12 = a12[j].f.x * a12[j].f.y;
                const float s12v = a5[j] - mu12;
                num[j] = fmaf(2.f, mu12, SSIM_C1) * fmaf(2.f, s12v, SSIM_C2);
                den[j] = (musq.f.x + musq.f.y + SSIM_C1) * (sig.f.x + sig.f.y + SSIM_C2);
            }

            // One division per 4 pixels (den >= ~9e-8; products stay normal).
            #pragma unroll
            for (int h2 = 0; h2 < 2; h2++) {
                const int b = 4 * h2;
                const float n01 = fmaf(num[b + 0], den[b + 1], num[b + 1] * den[b + 0]);
                const float d01 = den[b + 0] * den[b + 1];
                const float n23 = fmaf(num[b + 2], den[b + 3], num[b + 3] * den[b + 2]);
                const float d23 = den[b + 2] * den[b + 3];
                const float nall = fmaf(n01, d23, n23 * d01);
                const float dall = d01 * d23;
                ssum += __fdividef(nall, dall);
            }

            sc += 32; if (sc >= 42) sc -= 42;
        } else if (c < 3) {
            // ---- load next chunk's 32 rows (warps 4-7) -------------------
            const int w4 = wrp - 4;
            const int i0 = Y0 + 32 * (c + 1) + RAD;
            #pragma unroll 1
            for (int r = w4; r < 32; r += 4)
                load_row(spt, r, pb, tb, i0 + r, x0, xin, lane);
        }
        __syncthreads();

        if (c < 3) {
            // ---- hpass chunk c+1: exactly 256 items, r = lane, g = wrp --
            int slot = s2 + lane; if (slot >= 42) slot -= 42;
            hpass_one(spt, hb1234, hb5, GWp, GWs, lane, wrp * 4, slot);
            s2 += 32; if (s2 >= 42) s2 -= 42;
            __syncthreads();
        }
    }

    // ---- Block reduction -------------------------------------------------
    if (wrp < 4) {
        #pragma unroll
        for (int o = 16; o > 0; o >>= 1)
            ssum += __shfl_xor_sync(0xffffffffu, ssum, o);
        if (lane == 0) wsum[wrp] = ssum;
    }
    __syncthreads();

    if (tid == 0) {
        g_bsum[bid] = wsum[0] + wsum[1] + wsum[2] + wsum[3];
        __threadfence();
        const int old = atomicAdd(&g_cnt, 1);
        s_last = (old == NBLK - 1) ? 1 : 0;
    }
    __syncthreads();

    // ---- Last block: final reduction ------------------------------------
    if (s_last) {
        __threadfence();
        double acc0 = 0.0, acc1 = 0.0, acc2 = 0.0, acc3 = 0.0;
        #pragma unroll 1
        for (int i = tid; i < NBLK; i += 1024) {   // 3 iterations, 4-way MLP
            acc0 += (double)g_bsum[i];
            acc1 += (double)g_bsum[i + 256];
            acc2 += (double)g_bsum[i + 512];
            acc3 += (double)g_bsum[i + 768];
        }
        double d = (acc0 + acc1) + (acc2 + acc3);
        #pragma unroll
        for (int o = 16; o > 0; o >>= 1)
            d += __shfl_xor_sync(0xffffffffu, d, o);
        if (lane == 0) dsum[wrp] = d;
        __syncthreads();
        if (tid == 0) {
            double tot = 0.0;
            #pragma unroll
            for (int i = 0; i < 8; i++) tot += dsum[i];
            out[0] = (float)(1.0 - tot / 12582912.0);   // 16*3*512*512
            g_cnt = 0;                                   // reset for next replay
        }
    }
}

extern "C" void kernel_launch(void* const* d_in, const int* in_sizes, int n_in,
                              void* d_out, int out_size)
{
    const float* pred   = (const float*)d_in[0];
    const float* target = (const float*)d_in[1];
    (void)in_sizes; (void)n_in; (void)out_size;

    dim3 grid(64, NIMG);   // 16 x-strips * 4 y-strips, 48 images
    ssim_strip<<<grid, 256>>>(pred, target, (float*)d_out);
}

// round 9
// speedup vs baseline: 1.4287x; 1.4287x over previous
#include <cuda_runtime.h>

// SSIM loss, single fused kernel, f32x2-packed separable blur, 4 blur fields.
// pred/target: (16,3,512,512) f32. Output: scalar f32 = 1 - mean(ssim_map).
// Fields blurred: (p, t) packed and Q = (p^2 + t^2, (p+t)^2) packed.
// Then sigma1^2+sigma2^2 = A - mu1^2 - mu2^2, 2*sigma12 = (B - A) - 2*mu1*mu2.

#define RAD 5
#define TX 32
#define TY 32
#define PH 42                 // TY + 2*RAD
#define PW 42                 // TX + 2*RAD
#define HB4P 33               // float4 pitch: 528B = 16 mod 128 -> conflict-free
#define IMG 512
#define NIMG 48
#define TILES 256             // 16 x 16 tiles per image
#define NBLK (TILES * NIMG)   // 12288
#define SSIM_C1 1.0e-4f
#define SSIM_C2 9.0e-4f

__device__ float g_bsum[NBLK];
__device__ int g_cnt;         // zero-init; last block resets each run

union F2U { float2 f; unsigned long long u; };

__device__ __forceinline__ unsigned long long pack2(float x, float y) {
    unsigned long long r;
    asm("mov.b64 %0, {%1, %2};" : "=l"(r) : "f"(x), "f"(y));
    return r;
}
__device__ __forceinline__ unsigned long long fma2(unsigned long long a,
                                                   unsigned long long b,
                                                   unsigned long long c) {
    unsigned long long d;
    asm("fma.rn.f32x2 %0, %1, %2, %3;" : "=l"(d) : "l"(a), "l"(b), "l"(c));
    return d;
}
__device__ __forceinline__ unsigned long long mul2(unsigned long long a,
                                                   unsigned long long b) {
    unsigned long long d;
    asm("mul.rn.f32x2 %0, %1, %2;" : "=l"(d) : "l"(a), "l"(b));
    return d;
}

__global__ __launch_bounds__(256, 5)
void ssim_fused(const float* __restrict__ pred,
                const float* __restrict__ target,
                float* __restrict__ out)
{
    __shared__ float2 spt[PH][PW];            // (p,t) interleaved, pitch 336B
    __shared__ float4 hb[PH][HB4P];           // (h(p), h(t), h(A), h(B))
    __shared__ float  wsum[4];
    __shared__ double dsum[8];
    __shared__ int    s_last;

    // Normalized 1-D Gaussian, sigma=1.5, size 11 (literals -> FFMA-imm forms).
    const float GWs[11] = {
        0.00102838f, 0.00759876f, 0.03600077f, 0.10936069f, 0.21300553f,
        0.26601173f,
        0.21300553f, 0.10936069f, 0.03600077f, 0.00759876f, 0.00102838f
    };
    unsigned long long GWp[11];
    #pragma unroll
    for (int k = 0; k < 11; k++) GWp[k] = pack2(GWs[k], GWs[k]);

    const int tid  = threadIdx.x;
    const int lane = tid & 31;
    const int wrp  = tid >> 5;

    const int tile_x = blockIdx.x & 15;
    const int tile_y = blockIdx.x >> 4;
    const int bid    = blockIdx.y * TILES + blockIdx.x;
    const float* pb = pred   + (size_t)blockIdx.y * IMG * IMG;
    const float* tb = target + (size_t)blockIdx.y * IMG * IMG;
    const int x0 = tile_x * TX - RAD;
    const int y0 = tile_y * TY - RAD;

    // ---- Phase 1: load 42x42 halo, interleave (p,t) ---------------------
    const bool interior = (tile_x > 0) && (tile_x < 15) && (tile_y > 0) && (tile_y < 15);
    if (interior) {
        #pragma unroll 1
        for (int r = wrp; r < PH; r += 8) {
            const float* prow = pb + (y0 + r) * IMG + x0;
            const float* trow = tb + (y0 + r) * IMG + x0;
            spt[r][lane] = make_float2(__ldg(prow + lane), __ldg(trow + lane));
            if (lane < PW - 32)
                spt[r][lane + 32] = make_float2(__ldg(prow + lane + 32),
                                                __ldg(trow + lane + 32));
        }
    } else {
        #pragma unroll 1
        for (int r = wrp; r < PH; r += 8) {
            const int gy = y0 + r;
            const bool rok = ((unsigned)gy < (unsigned)IMG);
            const float* prow = pb + gy * IMG;
            const float* trow = tb + gy * IMG;
            {
                const int gx = x0 + lane;
                const bool ok = rok && ((unsigned)gx < (unsigned)IMG);
                spt[r][lane] = make_float2(ok ? __ldg(prow + gx) : 0.f,
                                           ok ? __ldg(trow + gx) : 0.f);
            }
            if (lane < PW - 32) {
                const int gx = x0 + lane + 32;
                const bool ok = rok && ((unsigned)gx < (unsigned)IMG);
                spt[r][lane + 32] = make_float2(ok ? __ldg(prow + gx) : 0.f,
                                                ok ? __ldg(trow + gx) : 0.f);
            }
        }
    }
    __syncthreads();

    // ---- Phase 2: horizontal blur, 4 output cols/thread -----------------
    // item = g*42 + r (lanes run along rows -> all LDS/STS conflict-free).
    // 336 items: half 0 = 256 threads, half 1 = 80 threads (2.5 warps).
    #pragma unroll
    for (int half = 0; half < 2; half++) {
        const int it = tid + half * 256;
        if (it < PH * 8) {
            const int g  = it / PH;
            const int r  = it - g * PH;
            const int cx = g * 4;

            float4 raw[7];
            const float4* rp = reinterpret_cast<const float4*>(&spt[r][cx]);
            #pragma unroll
            for (int q = 0; q < 7; q++) raw[q] = rp[q];

            F2U acc12[4], accQ[4];
            #pragma unroll
            for (int j = 0; j < 4; j++) {
                acc12[j].f = make_float2(0.f, 0.f);
                accQ[j].f  = make_float2(0.f, 0.f);
            }

            #pragma unroll
            for (int k = 0; k < 14; k++) {
                F2U e;
                e.f.x = (k & 1) ? raw[k >> 1].z : raw[k >> 1].x;
                e.f.y = (k & 1) ? raw[k >> 1].w : raw[k >> 1].y;
                F2U sq; sq.u = mul2(e.u, e.u);          // (p^2, t^2)
                const float s = e.f.x + e.f.y;           // p + t
                F2U q;
                q.f.x = sq.f.x + sq.f.y;                 // A = p^2 + t^2
                q.f.y = s * s;                           // B = (p+t)^2
                #pragma unroll
                for (int j = 0; j < 4; j++) {
                    const int w = k - j;
                    if (w >= 0 && w < 11) {
                        acc12[j].u = fma2(GWp[w], e.u, acc12[j].u);
                        accQ[j].u  = fma2(GWp[w], q.u, accQ[j].u);
                    }
                }
            }

            #pragma unroll
            for (int j = 0; j < 4; j++)
                hb[r][cx + j] = make_float4(acc12[j].f.x, acc12[j].f.y,
                                            accQ[j].f.x,  accQ[j].f.y);
        }
    }
    __syncthreads();

    // ---- Phase 3: vertical blur, warps 0-3, 8 rows/thread + SSIM --------
    if (wrp < 4) {
        const int c  = lane;
        const int yb = wrp * 8;

        F2U a12[8], aQ[8];
        #pragma unroll
        for (int j = 0; j < 8; j++) {
            a12[j].f = make_float2(0.f, 0.f);
            aQ[j].f  = make_float2(0.f, 0.f);
        }

        #pragma unroll
        for (int k = 0; k < 18; k++) {
            const float4 h = hb[yb + k][c];
            F2U h12; h12.f = make_float2(h.x, h.y);
            F2U hQ;  hQ.f  = make_float2(h.z, h.w);
            #pragma unroll
            for (int j = 0; j < 8; j++) {
                const int w = k - j;
                if (w >= 0 && w < 11) {
                    a12[j].u = fma2(GWp[w], h12.u, a12[j].u);
                    aQ[j].u  = fma2(GWp[w], hQ.u,  aQ[j].u);
                }
            }
        }

        float num[8], den[8];
        #pragma unroll
        for (int j = 0; j < 8; j++) {
            F2U musq; musq.u = mul2(a12[j].u, a12[j].u);    // (mu1^2, mu2^2)
            const float mu12 = a12[j].f.x * a12[j].f.y;      // mu1*mu2
            const float A    = aQ[j].f.x;                    // E[p^2]+E[t^2]
            const float B    = aQ[j].f.y;                    // E[(p+t)^2]
            const float ssum2 = musq.f.x + musq.f.y;         // mu1^2+mu2^2
            // num = (2 mu12 + C1) * ((B - A) - 2 mu12 + C2)
            // den = (mu1^2+mu2^2 + C1) * (A - mu1^2 - mu2^2 + C2)
            num[j] = fmaf(2.f, mu12, SSIM_C1) *
                     fmaf(-2.f, mu12, (B - A) + SSIM_C2);
            den[j] = (ssum2 + SSIM_C1) * ((A + SSIM_C2) - ssum2);
        }

        // One division per 4 pixels (den >= ~9e-8; 4-way product stays normal).
        float ssum = 0.f;
        #pragma unroll
        for (int h2 = 0; h2 < 2; h2++) {
            const int b = 4 * h2;
            const float n01 = fmaf(num[b + 0], den[b + 1], num[b + 1] * den[b + 0]);
            const float d01 = den[b + 0] * den[b + 1];
            const float n23 = fmaf(num[b + 2], den[b + 3], num[b + 3] * den[b + 2]);
            const float d23 = den[b + 2] * den[b + 3];
            const float nall = fmaf(n01, d23, n23 * d01);
            const float dall = d01 * d23;
            ssum += __fdividef(nall, dall);
        }

        #pragma unroll
        for (int o = 16; o > 0; o >>= 1)
            ssum += __shfl_xor_sync(0xffffffffu, ssum, o);
        if (lane == 0) wsum[wrp] = ssum;
    }
    __syncthreads();

    // ---- Per-block sum + last-block-done global reduction ---------------
    if (tid == 0) {
        g_bsum[bid] = wsum[0] + wsum[1] + wsum[2] + wsum[3];
        __threadfence();
        const int old = atomicAdd(&g_cnt, 1);
        s_last = (old == NBLK - 1) ? 1 : 0;
    }
    __syncthreads();

    if (s_last) {
        __threadfence();
        double acc0 = 0.0, acc1 = 0.0, acc2 = 0.0, acc3 = 0.0;
        #pragma unroll 1
        for (int i = tid; i < NBLK; i += 1024) {   // 12 iterations, 4-way MLP
            acc0 += (double)g_bsum[i];
            acc1 += (double)g_bsum[i + 256];
            acc2 += (double)g_bsum[i + 512];
            acc3 += (double)g_bsum[i + 768];
        }
        double d = (acc0 + acc1) + (acc2 + acc3);
        #pragma unroll
        for (int o = 16; o > 0; o >>= 1)
            d += __shfl_xor_sync(0xffffffffu, d, o);
        if (lane == 0) dsum[wrp] = d;
        __syncthreads();
        if (tid == 0) {
            double tot = 0.0;
            #pragma unroll
            for (int i = 0; i < 8; i++) tot += dsum[i];
            out[0] = (float)(1.0 - tot / 12582912.0);   // 16*3*512*512
            g_cnt = 0;                                   // reset for next replay
        }
    }
}

extern "C" void kernel_launch(void* const* d_in, const int* in_sizes, int n_in,
                              void* d_out, int out_size)
{
    const float* pred   = (const float*)d_in[0];
    const float* target = (const float*)d_in[1];
    (void)in_sizes; (void)n_in; (void)out_size;

    dim3 grid(TILES, NIMG);   // (256, 48)
    ssim_fused<<<grid, 256>>>(pred, target, (float*)d_out);
}

// round 10
// speedup vs baseline: 1.5162x; 1.0613x over previous
#include <cuda_runtime.h>

// SSIM loss, single fused kernel, f32x2-packed separable blur, 4 blur fields.
// pred/target: (16,3,512,512) f32. Output: scalar f32 = 1 - mean(ssim_map).
// Fields blurred: (p, t) packed and Q = (p^2 + t^2, p*t) packed.
// Then sigma1^2+sigma2^2 = A - mu1^2 - mu2^2, sigma12 = E[pt] - mu1*mu2.

#define RAD 5
#define TX 32
#define TY 32
#define PH 42                 // TY + 2*RAD
#define PW 42                 // TX + 2*RAD
#define HB4P 33               // float4 pitch: 528B = 16 mod 128 -> conflict-free
#define IMG 512
#define NIMG 48
#define TILES 256             // 16 x 16 tiles per image
#define NBLK (TILES * NIMG)   // 12288
#define SSIM_C1 1.0e-4f
#define SSIM_C2 9.0e-4f

__device__ float g_bsum[NBLK];
__device__ int g_cnt;         // zero-init; last block resets each run

union F2U { float2 f; unsigned long long u; };

__device__ __forceinline__ unsigned long long pack2(float x, float y) {
    unsigned long long r;
    asm("mov.b64 %0, {%1, %2};" : "=l"(r) : "f"(x), "f"(y));
    return r;
}
__device__ __forceinline__ unsigned long long fma2(unsigned long long a,
                                                   unsigned long long b,
                                                   unsigned long long c) {
    unsigned long long d;
    asm("fma.rn.f32x2 %0, %1, %2, %3;" : "=l"(d) : "l"(a), "l"(b), "l"(c));
    return d;
}
__device__ __forceinline__ unsigned long long mul2(unsigned long long a,
                                                   unsigned long long b) {
    unsigned long long d;
    asm("mul.rn.f32x2 %0, %1, %2;" : "=l"(d) : "l"(a), "l"(b));
    return d;
}

__global__ __launch_bounds__(256, 6)
void ssim_fused(const float* __restrict__ pred,
                const float* __restrict__ target,
                float* __restrict__ out)
{
    __shared__ float2 spt[PH][PW];            // (p,t) interleaved, pitch 336B
    __shared__ float4 hb[PH][HB4P];           // (h(p), h(t), h(A), h(pt))
    __shared__ float  wsum[4];
    __shared__ double dsum[8];
    __shared__ int    s_last;

    // Normalized 1-D Gaussian, sigma=1.5, size 11 (literals -> FFMA-imm forms).
    const float GWs[11] = {
        0.00102838f, 0.00759876f, 0.03600077f, 0.10936069f, 0.21300553f,
        0.26601173f,
        0.21300553f, 0.10936069f, 0.03600077f, 0.00759876f, 0.00102838f
    };
    unsigned long long GWp[11];
    #pragma unroll
    for (int k = 0; k < 11; k++) GWp[k] = pack2(GWs[k], GWs[k]);

    const int tid  = threadIdx.x;
    const int lane = tid & 31;
    const int wrp  = tid >> 5;

    const int tile_x = blockIdx.x & 15;
    const int tile_y = blockIdx.x >> 4;
    const int bid    = blockIdx.y * TILES + blockIdx.x;
    const float* pb = pred   + (size_t)blockIdx.y * IMG * IMG;
    const float* tb = target + (size_t)blockIdx.y * IMG * IMG;
    const int x0 = tile_x * TX - RAD;
    const int y0 = tile_y * TY - RAD;

    // ---- Phase 1: load 42x42 halo, interleave (p,t) ---------------------
    const bool interior = (tile_x > 0) && (tile_x < 15) && (tile_y > 0) && (tile_y < 15);
    if (interior) {
        #pragma unroll 1
        for (int r = wrp; r < PH; r += 8) {
            const float* prow = pb + (y0 + r) * IMG + x0;
            const float* trow = tb + (y0 + r) * IMG + x0;
            spt[r][lane] = make_float2(__ldg(prow + lane), __ldg(trow + lane));
            if (lane < PW - 32)
                spt[r][lane + 32] = make_float2(__ldg(prow + lane + 32),
                                                __ldg(trow + lane + 32));
        }
    } else {
        #pragma unroll 1
        for (int r = wrp; r < PH; r += 8) {
            const int gy = y0 + r;
            const bool rok = ((unsigned)gy < (unsigned)IMG);
            const float* prow = pb + gy * IMG;
            const float* trow = tb + gy * IMG;
            {
                const int gx = x0 + lane;
                const bool ok = rok && ((unsigned)gx < (unsigned)IMG);
                spt[r][lane] = make_float2(ok ? __ldg(prow + gx) : 0.f,
                                           ok ? __ldg(trow + gx) : 0.f);
            }
            if (lane < PW - 32) {
                const int gx = x0 + lane + 32;
                const bool ok = rok && ((unsigned)gx < (unsigned)IMG);
                spt[r][lane + 32] = make_float2(ok ? __ldg(prow + gx) : 0.f,
                                                ok ? __ldg(trow + gx) : 0.f);
            }
        }
    }
    __syncthreads();

    // ---- Phase 2: horizontal blur, 4 output cols/thread -----------------
    // item = g*42 + r (lanes run along rows -> all LDS/STS conflict-free).
    // 336 items: half 0 = 256 threads, half 1 = 80 threads (2.5 warps).
    #pragma unroll
    for (int half = 0; half < 2; half++) {
        const int it = tid + half * 256;
        if (it < PH * 8) {
            const int g  = it / PH;
            const int r  = it - g * PH;
            const int cx = g * 4;

            float4 raw[7];
            const float4* rp = reinterpret_cast<const float4*>(&spt[r][cx]);
            #pragma unroll
            for (int q = 0; q < 7; q++) raw[q] = rp[q];

            F2U acc12[4], accQ[4];
            #pragma unroll
            for (int j = 0; j < 4; j++) {
                acc12[j].f = make_float2(0.f, 0.f);
                accQ[j].f  = make_float2(0.f, 0.f);
            }

            #pragma unroll
            for (int k = 0; k < 14; k++) {
                F2U e;
                e.f.x = (k & 1) ? raw[k >> 1].z : raw[k >> 1].x;
                e.f.y = (k & 1) ? raw[k >> 1].w : raw[k >> 1].y;
                F2U sq; sq.u = mul2(e.u, e.u);          // (p^2, t^2)
                F2U q;
                q.f.x = sq.f.x + sq.f.y;                 // A  = p^2 + t^2
                q.f.y = e.f.x * e.f.y;                   // pt = p * t
                #pragma unroll
                for (int j = 0; j < 4; j++) {
                    const int w = k - j;
                    if (w >= 0 && w < 11) {
                        acc12[j].u = fma2(GWp[w], e.u, acc12[j].u);
                        accQ[j].u  = fma2(GWp[w], q.u, accQ[j].u);
                    }
                }
            }

            #pragma unroll
            for (int j = 0; j < 4; j++)
                hb[r][cx + j] = make_float4(acc12[j].f.x, acc12[j].f.y,
                                            accQ[j].f.x,  accQ[j].f.y);
        }
    }
    __syncthreads();

    // ---- Phase 3: vertical blur, warps 0-3, 8 rows/thread + SSIM --------
    if (wrp < 4) {
        const int c  = lane;
        const int yb = wrp * 8;

        F2U a12[8], aQ[8];
        #pragma unroll
        for (int j = 0; j < 8; j++) {
            a12[j].f = make_float2(0.f, 0.f);
            aQ[j].f  = make_float2(0.f, 0.f);
        }

        #pragma unroll
        for (int k = 0; k < 18; k++) {
            const float4 h = hb[yb + k][c];
            F2U h12; h12.f = make_float2(h.x, h.y);
            F2U hQ;  hQ.f  = make_float2(h.z, h.w);
            #pragma unroll
            for (int j = 0; j < 8; j++) {
                const int w = k - j;
                if (w >= 0 && w < 11) {
                    a12[j].u = fma2(GWp[w], h12.u, a12[j].u);
                    aQ[j].u  = fma2(GWp[w], hQ.u,  aQ[j].u);
                }
            }
        }

        float num[8], den[8];
        #pragma unroll
        for (int j = 0; j < 8; j++) {
            F2U musq; musq.u = mul2(a12[j].u, a12[j].u);    // (mu1^2, mu2^2)
            const float mu12  = a12[j].f.x * a12[j].f.y;     // mu1*mu2
            const float A     = aQ[j].f.x;                   // E[p^2]+E[t^2]
            const float Ept   = aQ[j].f.y;                   // E[pt]
            const float ssum2 = musq.f.x + musq.f.y;         // mu1^2+mu2^2
            const float s12v  = Ept - mu12;                  // sigma12
            num[j] = fmaf(2.f, mu12, SSIM_C1) * fmaf(2.f, s12v, SSIM_C2);
            den[j] = (ssum2 + SSIM_C1) * ((A + SSIM_C2) - ssum2);
        }

        // One division per 4 pixels (den >= ~9e-8; 4-way product stays normal).
        float ssum = 0.f;
        #pragma unroll
        for (int h2 = 0; h2 < 2; h2++) {
            const int b = 4 * h2;
            const float n01 = fmaf(num[b + 0], den[b + 1], num[b + 1] * den[b + 0]);
            const float d01 = den[b + 0] * den[b + 1];
            const float n23 = fmaf(num[b + 2], den[b + 3], num[b + 3] * den[b + 2]);
            const float d23 = den[b + 2] * den[b + 3];
            const float nall = fmaf(n01, d23, n23 * d01);
            const float dall = d01 * d23;
            ssum += __fdividef(nall, dall);
        }

        #pragma unroll
        for (int o = 16; o > 0; o >>= 1)
            ssum += __shfl_xor_sync(0xffffffffu, ssum, o);
        if (lane == 0) wsum[wrp] = ssum;
    }
    __syncthreads();

    // ---- Per-block sum + last-block-done global reduction ---------------
    if (tid == 0) {
        g_bsum[bid] = wsum[0] + wsum[1] + wsum[2] + wsum[3];
        __threadfence();
        const int old = atomicAdd(&g_cnt, 1);
        s_last = (old == NBLK - 1) ? 1 : 0;
    }
    __syncthreads();

    if (s_last) {
        __threadfence();
        double acc0 = 0.0, acc1 = 0.0, acc2 = 0.0, acc3 = 0.0;
        #pragma unroll 1
        for (int i = tid; i < NBLK; i += 1024) {   // 12 iterations, 4-way MLP
            acc0 += (double)g_bsum[i];
            acc1 += (double)g_bsum[i + 256];
            acc2 += (double)g_bsum[i + 512];
            acc3 += (double)g_bsum[i + 768];
        }
        double d = (acc0 + acc1) + (acc2 + acc3);
        #pragma unroll
        for (int o = 16; o > 0; o >>= 1)
            d += __shfl_xor_sync(0xffffffffu, d, o);
        if (lane == 0) dsum[wrp] = d;
        __syncthreads();
        if (tid == 0) {
            double tot = 0.0;
            #pragma unroll
            for (int i = 0; i < 8; i++) tot += dsum[i];
            out[0] = (float)(1.0 - tot / 12582912.0);   // 16*3*512*512
            g_cnt = 0;                                   // reset for next replay
        }
    }
}

extern "C" void kernel_launch(void* const* d_in, const int* in_sizes, int n_in,
                              void* d_out, int out_size)
{
    const float* pred   = (const float*)d_in[0];
    const float* target = (const float*)d_in[1];
    (void)in_sizes; (void)n_in; (void)out_size;

    dim3 grid(TILES, NIMG);   // (256, 48)
    ssim_fused<<<grid, 256>>>(pred, target, (float*)d_out);
}

// round 14
// speedup vs baseline: 1.5676x; 1.0339x over previous
#include <cuda_runtime.h>

// SSIM loss, single fused kernel, f32x2-packed separable blur, 4 blur fields.
// Phase 1 uses aligned float2 global loads (halo widened to even base col) and
// STS.128 interleaved stores. pred/target: (16,3,512,512) f32.
// Output: scalar f32 = 1 - mean(ssim_map).

#define RAD 5
#define TX 32
#define TY 32
#define PH 42                 // TY + 2*RAD rows
#define SPW2 46               // spt pitch in float2 (368B = 112 mod 128, 16B-mult)
#define HB4P 33               // float4 pitch: 528B = 16 mod 128 -> conflict-free
#define IMG 512
#define NIMG 48
#define TILES 256             // 16 x 16 tiles per image
#define NBLK (TILES * NIMG)   // 12288
#define SSIM_C1 1.0e-4f
#define SSIM_C2 9.0e-4f

__device__ float g_bsum[NBLK];
__device__ int g_cnt;         // zero-init; last block resets each run

union F2U { float2 f; unsigned long long u; };

__device__ __forceinline__ unsigned long long pack2(float x, float y) {
    unsigned long long r;
    asm("mov.b64 %0, {%1, %2};" : "=l"(r) : "f"(x), "f"(y));
    return r;
}
__device__ __forceinline__ unsigned long long fma2(unsigned long long a,
                                                   unsigned long long b,
                                                   unsigned long long c) {
    unsigned long long d;
    asm("fma.rn.f32x2 %0, %1, %2, %3;" : "=l"(d) : "l"(a), "l"(b), "l"(c));
    return d;
}
__device__ __forceinline__ unsigned long long mul2(unsigned long long a,
                                                   unsigned long long b) {
    unsigned long long d;
    asm("mul.rn.f32x2 %0, %1, %2;" : "=l"(d) : "l"(a), "l"(b));
    return d;
}

__global__ __launch_bounds__(256, 6)
void ssim_fused(const float* __restrict__ pred,
                const float* __restrict__ target,
                float* __restrict__ out)
{
    // spt[r][i] = (p, t) for image col (x0-1)+i ; halo cols are idx 1..42.
    __shared__ __align__(16) float2 spt[PH][SPW2];
    __shared__ float4 hb[PH][HB4P];           // (h(p), h(t), h(A), h(pt))
    __shared__ float  wsum[4];
    __shared__ double dsum[8];
    __shared__ int    s_last;

    // Normalized 1-D Gaussian, sigma=1.5, size 11 (literals -> FFMA-imm forms).
    const float GWs[11] = {
        0.00102838f, 0.00759876f, 0.03600077f, 0.10936069f, 0.21300553f,
        0.26601173f,
        0.21300553f, 0.10936069f, 0.03600077f, 0.00759876f, 0.00102838f
    };
    unsigned long long GWp[11];
    #pragma unroll
    for (int k = 0; k < 11; k++) GWp[k] = pack2(GWs[k], GWs[k]);

    const int tid  = threadIdx.x;
    const int lane = tid & 31;
    const int wrp  = tid >> 5;

    const int tile_x = blockIdx.x & 15;
    const int tile_y = blockIdx.x >> 4;
    const int bid    = blockIdx.y * TILES + blockIdx.x;
    const float* pb = pred   + (size_t)blockIdx.y * IMG * IMG;
    const float* tb = target + (size_t)blockIdx.y * IMG * IMG;
    const int xm1 = tile_x * TX - RAD - 1;    // even; spt idx 0 = this image col
    const int y0  = tile_y * TY - RAD;

    // ---- Phase 1: load halo as aligned float2 pairs ---------------------
    // Pair i covers image cols xm1+2i, xm1+2i+1; both in or both out
    // (xm1 even, image edges 0/512 even). 22 pairs per row.
    const bool interior = (tile_x > 0) && (tile_x < 15) && (tile_y > 0) && (tile_y < 15);
    if (interior) {
        #pragma unroll 1
        for (int r = wrp; r < PH; r += 8) {
            if (lane < 22) {
                const float2* prow = reinterpret_cast<const float2*>(pb + (y0 + r) * IMG + xm1);
                const float2* trow = reinterpret_cast<const float2*>(tb + (y0 + r) * IMG + xm1);
                const float2 pv = __ldg(prow + lane);
                const float2 tv = __ldg(trow + lane);
                *reinterpret_cast<float4*>(&spt[r][2 * lane]) =
                    make_float4(pv.x, tv.x, pv.y, tv.y);
            }
        }
    } else {
        #pragma unroll 1
        for (int r = wrp; r < PH; r += 8) {
            if (lane < 22) {
                const int gy = y0 + r;
                const int gx = xm1 + 2 * lane;
                const bool ok = ((unsigned)gy < (unsigned)IMG) &&
                                ((unsigned)gx < (unsigned)IMG);
                float2 pv = make_float2(0.f, 0.f);
                float2 tv = make_float2(0.f, 0.f);
                if (ok) {
                    pv = __ldg(reinterpret_cast<const float2*>(pb + gy * IMG + gx));
                    tv = __ldg(reinterpret_cast<const float2*>(tb + gy * IMG + gx));
                }
                *reinterpret_cast<float4*>(&spt[r][2 * lane]) =
                    make_float4(pv.x, tv.x, pv.y, tv.y);
            }
        }
    }
    __syncthreads();

    // ---- Phase 2: horizontal blur, 4 output cols/thread -----------------
    // item = g*42 + r. Output col cx+j (image col 32*tx+cx+j) needs spt
    // indices cx+j+1 .. cx+j+11 -> raw window spt[cx .. cx+15] (8x LDS.128).
    #pragma unroll
    for (int half = 0; half < 2; half++) {
        const int it = tid + half * 256;
        if (it < PH * 8) {
            const int g  = it / PH;
            const int r  = it - g * PH;
            const int cx = g * 4;

            float4 raw4[8];
            const float4* rp = reinterpret_cast<const float4*>(&spt[r][cx]);
            #pragma unroll
            for (int q = 0; q < 8; q++) raw4[q] = rp[q];
            const float2* rw = reinterpret_cast<const float2*>(raw4);

            F2U acc12[4], accQ[4];
            #pragma unroll
            for (int j = 0; j < 4; j++) {
                acc12[j].f = make_float2(0.f, 0.f);
                accQ[j].f  = make_float2(0.f, 0.f);
            }

            #pragma unroll
            for (int k = 1; k < 15; k++) {
                F2U e; e.f = rw[k];
                F2U sq; sq.u = mul2(e.u, e.u);          // (p^2, t^2)
                F2U q;
                q.f.x = sq.f.x + sq.f.y;                 // A  = p^2 + t^2
                q.f.y = e.f.x * e.f.y;                   // pt = p * t
                #pragma unroll
                for (int j = 0; j < 4; j++) {
                    const int w = k - 1 - j;
                    if (w >= 0 && w < 11) {
                        acc12[j].u = fma2(GWp[w], e.u, acc12[j].u);
                        accQ[j].u  = fma2(GWp[w], q.u, accQ[j].u);
                    }
                }
            }

            #pragma unroll
            for (int j = 0; j < 4; j++)
                hb[r][cx + j] = make_float4(acc12[j].f.x, acc12[j].f.y,
                                            accQ[j].f.x,  accQ[j].f.y);
        }
    }
    __syncthreads();

    // ---- Phase 3: vertical blur, warps 0-3, 8 rows/thread + SSIM --------
    if (wrp < 4) {
        const int c  = lane;
        const int yb = wrp * 8;

        F2U a12[8], aQ[8];
        #pragma unroll
        for (int j = 0; j < 8; j++) {
            a12[j].f = make_float2(0.f, 0.f);
            aQ[j].f  = make_float2(0.f, 0.f);
        }

        #pragma unroll
        for (int k = 0; k < 18; k++) {
            const float4 h = hb[yb + k][c];
            F2U h12; h12.f = make_float2(h.x, h.y);
            F2U hQ;  hQ.f  = make_float2(h.z, h.w);
            #pragma unroll
            for (int j = 0; j < 8; j++) {
                const int w = k - j;
                if (w >= 0 && w < 11) {
                    a12[j].u = fma2(GWp[w], h12.u, a12[j].u);
                    aQ[j].u  = fma2(GWp[w], hQ.u,  aQ[j].u);
                }
            }
        }

        float num[8], den[8];
        #pragma unroll
        for (int j = 0; j < 8; j++) {
            F2U musq; musq.u = mul2(a12[j].u, a12[j].u);    // (mu1^2, mu2^2)
            const float mu12  = a12[j].f.x * a12[j].f.y;     // mu1*mu2
            const float A     = aQ[j].f.x;                   // E[p^2]+E[t^2]
            const float Ept   = aQ[j].f.y;                   // E[pt]
            const float ssum2 = musq.f.x + musq.f.y;         // mu1^2+mu2^2
            const float s12v  = Ept - mu12;                  // sigma12
            num[j] = fmaf(2.f, mu12, SSIM_C1) * fmaf(2.f, s12v, SSIM_C2);
            den[j] = (ssum2 + SSIM_C1) * ((A + SSIM_C2) - ssum2);
        }

        // One division per 4 pixels (den >= ~9e-8; 4-way product stays normal).
        float ssum = 0.f;
        #pragma unroll
        for (int h2 = 0; h2 < 2; h2++) {
            const int b = 4 * h2;
            const float n01 = fmaf(num[b + 0], den[b + 1], num[b + 1] * den[b + 0]);
            const float d01 = den[b + 0] * den[b + 1];
            const float n23 = fmaf(num[b + 2], den[b + 3], num[b + 3] * den[b + 2]);
            const float d23 = den[b + 2] * den[b + 3];
            const float nall = fmaf(n01, d23, n23 * d01);
            const float dall = d01 * d23;
            ssum += __fdividef(nall, dall);
        }

        #pragma unroll
        for (int o = 16; o > 0; o >>= 1)
            ssum += __shfl_xor_sync(0xffffffffu, ssum, o);
        if (lane == 0) wsum[wrp] = ssum;
    }
    __syncthreads();

    // ---- Per-block sum + last-block-done global reduction ---------------
    if (tid == 0) {
        g_bsum[bid] = wsum[0] + wsum[1] + wsum[2] + wsum[3];
        __threadfence();
        const int old = atomicAdd(&g_cnt, 1);
        s_last = (old == NBLK - 1) ? 1 : 0;
    }
    __syncthreads();

    if (s_last) {
        __threadfence();
        double acc0 = 0.0, acc1 = 0.0, acc2 = 0.0, acc3 = 0.0;
        #pragma unroll 1
        for (int i = tid; i < NBLK; i += 1024) {   // 12 iterations, 4-way MLP
            acc0 += (double)g_bsum[i];
            acc1 += (double)g_bsum[i + 256];
            acc2 += (double)g_bsum[i + 512];
            acc3 += (double)g_bsum[i + 768];
        }
        double d = (acc0 + acc1) + (acc2 + acc3);
        #pragma unroll
        for (int o = 16; o > 0; o >>= 1)
            d += __shfl_xor_sync(0xffffffffu, d, o);
        if (lane == 0) dsum[wrp] = d;
        __syncthreads();
        if (tid == 0) {
            double tot = 0.0;
            #pragma unroll
            for (int i = 0; i < 8; i++) tot += dsum[i];
            out[0] = (float)(1.0 - tot / 12582912.0);   // 16*3*512*512
            g_cnt = 0;                                   // reset for next replay
        }
    }
}

extern "C" void kernel_launch(void* const* d_in, const int* in_sizes, int n_in,
                              void* d_out, int out_size)
{
    const float* pred   = (const float*)d_in[0];
    const float* target = (const float*)d_in[1];
    (void)in_sizes; (void)n_in; (void)out_size;

    dim3 grid(TILES, NIMG);   // (256, 48)
    ssim_fused<<<grid, 256>>>(pred, target, (float*)d_out);
}